// round 9
// baseline (speedup 1.0000x reference)
#include <cuda_runtime.h>
#include <cstdint>

#define NSTEPS 10
#define NB     512     // grid blocks (all co-resident: 148 SMs x 4 blocks = 592 slots)
#define NT     256
#define NBAR   14      // exactly NBAR barriers per run; slot k reset during barrier (k+1)%NBAR
#define NELEMS 262144
#define MASK52 ((1ull << 52) - 1ull)
#define CNT1   (1ull << 52)
#define WSTRIDE 76     // smem row stride (floats): float4-aligned, conflict-free

// ---------------- device scratch ----------------
__device__ float g_C[16 * 2048];            // chunk sums of W1 (8 rows each)
__device__ float g_pre1[4096 * 32];         // base hidden pre-activation (+b1)
__device__ float g_accout[128 * 64];        // final-gather acc rows
__device__ float g_err32[32];               // per-b steploss accumulations
__device__ float g_abspart[NB];

// hierarchical barrier state: 256B-padded slots to spread across LTS slices
struct GSlot { unsigned long long v; unsigned long long pad[31]; };
__device__ GSlot g_grp[NBAR][32];           // per-group (count<<52 | fp-sum)
__device__ GSlot g_root[NBAR];              // root (count<<52 | fp-sum)
__device__ GSlot g_bc[NBAR];                // broadcast: bit63 ready | fp-sum

struct Keys { unsigned k0[NSTEPS]; unsigned k1[NSTEPS]; };

// ---------------- threefry2x32 ----------------
#define TF_ROT(x, r) (((x) << (r)) | ((x) >> (32 - (r))))
__host__ __device__ __forceinline__ void tf2x32(unsigned k0, unsigned k1,
                                                unsigned x0, unsigned x1,
                                                unsigned* o0, unsigned* o1) {
  unsigned ks0 = k0, ks1 = k1, ks2 = k0 ^ k1 ^ 0x1BD11BDAu;
  x0 += ks0; x1 += ks1;
#define TF_R4(a,b,c,d) \
  x0 += x1; x1 = TF_ROT(x1,a); x1 ^= x0; \
  x0 += x1; x1 = TF_ROT(x1,b); x1 ^= x0; \
  x0 += x1; x1 = TF_ROT(x1,c); x1 ^= x0; \
  x0 += x1; x1 = TF_ROT(x1,d); x1 ^= x0;
  TF_R4(13,15,26,6)  x0 += ks1; x1 += ks2 + 1u;
  TF_R4(17,29,16,24) x0 += ks2; x1 += ks0 + 2u;
  TF_R4(13,15,26,6)  x0 += ks0; x1 += ks1 + 3u;
  TF_R4(17,29,16,24) x0 += ks1; x1 += ks2 + 4u;
  TF_R4(13,15,26,6)  x0 += ks2; x1 += ks0 + 5u;
#undef TF_R4
  *o0 = x0; *o1 = x1;
}

__device__ __forceinline__ unsigned tfxor(unsigned k0, unsigned k1, unsigned e) {
  unsigned o0, o1;
  tf2x32(k0, k1, 0u, e, &o0, &o1);
  return o0 ^ o1;
}

// bits -> uniform -> sqrt(2)*erfinv (XLA/Giles f32 polynomial)
__device__ __forceinline__ float bits_to_normal(unsigned bits) {
  float f = __uint_as_float((bits >> 9) | 0x3f800000u) - 1.0f;
  const float lo = __uint_as_float(0xBF7FFFFFu);
  float u = fmaxf(lo, f * 2.0f + lo);
  float w = -log1pf(-u * u);
  float p;
  if (w < 5.0f) {
    w -= 2.5f;
    p = 2.81022636e-08f;
    p = fmaf(p, w, 3.43273939e-07f);
    p = fmaf(p, w, -3.5233877e-06f);
    p = fmaf(p, w, -4.39150654e-06f);
    p = fmaf(p, w, 0.00021858087f);
    p = fmaf(p, w, -0.00125372503f);
    p = fmaf(p, w, -0.00417768164f);
    p = fmaf(p, w, 0.246640727f);
    p = fmaf(p, w, 1.50140941f);
  } else {
    w = sqrtf(w) - 3.0f;
    p = -0.000200214257f;
    p = fmaf(p, w, 0.000100950558f);
    p = fmaf(p, w, 0.00134934322f);
    p = fmaf(p, w, -0.00367342844f);
    p = fmaf(p, w, 0.00573950773f);
    p = fmaf(p, w, -0.0076224613f);
    p = fmaf(p, w, 0.00943887047f);
    p = fmaf(p, w, 1.00167406f);
    p = fmaf(p, w, 2.83297682f);
  }
  return 1.41421356237f * (p * u);
}

__device__ __forceinline__ float wred(float v) {
#pragma unroll
  for (int o = 16; o; o >>= 1) v += __shfl_xor_sync(0xffffffffu, v, o);
  return v;
}

// Hierarchical barrier + deterministic sum (fixed-point, associative).
// Called by tid0 only. 16 blocks/group slot -> 32 group leaders hit root ->
// last root arriver broadcasts (bit63 | total). Resets: group leader at k
// resets its group slot of k-1 (its 16 members all passed k-1); root-last at k
// resets root(k-1) and bc(k-1) (all 512 passed k-1's poll). Replay-safe: slot 13
// is reset during barrier 0 of the next run, before its reuse.
__device__ __forceinline__ float barrier_sum(int k, float bp) {
  const int prev = (k + NBAR - 1) % NBAR;
  const int g = blockIdx.x >> 4;
  const unsigned long long add = ((unsigned long long)(bp * 4294967296.0f)) + CNT1;
  const unsigned long long old = atomicAdd(&g_grp[k][g].v, add);
  if ((old >> 52) == 15ull) {                       // last arriver in group
    const unsigned long long gsum = (old + add) & MASK52;
    atomicExch(&g_grp[prev][g].v, 0ull);            // reset prev group slot
    const unsigned long long radd = gsum + CNT1;
    const unsigned long long rold = atomicAdd(&g_root[k].v, radd);
    if ((rold >> 52) == 31ull) {                    // last root arriver
      const unsigned long long total = (rold + radd) & MASK52;
      atomicExch(&g_root[prev].v, 0ull);
      __threadfence();
      *((volatile unsigned long long*)&g_bc[k].v) = total | (1ull << 63);
      *((volatile unsigned long long*)&g_bc[prev].v) = 0ull;
      return (float)((double)total * (1.0 / 4294967296.0));
    }
  }
  unsigned long long v;
  do { v = *((volatile unsigned long long*)&g_bc[k].v); } while (!(v >> 63));
  return (float)((double)(v & MASK52) * (1.0 / 4294967296.0));
}

// ---------------- the one fused kernel ----------------
__global__ void __launch_bounds__(NT, 4) kFused(
    const float* __restrict__ emb, const float* __restrict__ W1,
    const float* __restrict__ b1,  const float* __restrict__ W2,
    const float* __restrict__ b2,  float* __restrict__ out, Keys K) {
  __shared__ __align__(16) float sWT[32 * WSTRIDE];   // W1 tile transposed: [h][d]
  __shared__ __align__(16) union {
    float S[2048];                                    // prologue suffix sums
    float W2T[64 * WSTRIDE];                          // W2 transposed: [c][hh]
  } U;
  __shared__ __align__(16) float sAcc[8][64];         // per-warp acc staging
  __shared__ __align__(16) float sH[8][32];           // per-warp hidden staging
  __shared__ float sRed[256];
  __shared__ float sb2s[64];
  __shared__ float swts[32];

  const int p = blockIdx.x;
  const int tid = threadIdx.x;
  const int lane = tid & 31, w = tid >> 5;
  const int t = p & 127;

  // W1 tile transposed: sWT[h][d] = W1[t*2048 + d*32 + h]
  for (int i = tid; i < 2048; i += NT)
    sWT[(i & 31) * WSTRIDE + (i >> 5)] = W1[t * 2048 + i];
  if (tid < 64) sb2s[tid] = b2[tid];
  if (tid < 32) swts[tid] = W1[262144 + tid];

  // ---- P0: chunk sums C[c][q] = sum of W1 rows 8c..8c+7 ----
  if (p < 16) {
    for (int qq = tid; qq < 2048; qq += NT) {
      float s = 0.0f;
#pragma unroll
      for (int r = 0; r < 8; ++r) s += W1[(p * 8 + r) * 2048 + qq];
      __stcg(&g_C[p * 2048 + qq], s);
    }
    __threadfence();
  }
  __syncthreads();
  if (tid == 0) { barrier_sum(0, 0.0f); }
  __syncthreads();
  __threadfence();

  // ---- P1: S[j] suffix sums + pre1 rows for j = p (blocks 0..127) ----
  if (p < 128) {
    const int j = p, cj = j >> 3;
    for (int qq = tid; qq < 2048; qq += NT) {
      float s = 0.0f;
      for (int c = cj + 1; c < 16; ++c) s += __ldcg(&g_C[c * 2048 + qq]);
      for (int tt = j + 1; tt < cj * 8 + 8; ++tt) s += W1[tt * 2048 + qq];
      U.S[qq] = s;
    }
    __syncthreads();
    const int o = tid * 4;
    const int b = o >> 5, hh = o & 31;
    float v0 = b1[hh], v1 = b1[hh + 1], v2 = b1[hh + 2], v3 = b1[hh + 3];
    const float* er = emb + b * 8192 + j * 64;
#pragma unroll 8
    for (int d = 0; d < 64; ++d) {
      float ev = er[d];
      const float* sp = &U.S[d * 32 + hh];
      v0 = fmaf(ev, sp[0], v0); v1 = fmaf(ev, sp[1], v1);
      v2 = fmaf(ev, sp[2], v2); v3 = fmaf(ev, sp[3], v3);
    }
    float* pp = &g_pre1[(j * 32 + b) * 32 + hh];
    pp[0] = v0; pp[1] = v1; pp[2] = v2; pp[3] = v3;
    __threadfence();
  }
  __syncthreads();
  if (tid == 0) { barrier_sum(1, 0.0f); }
  __syncthreads();
  __threadfence();

  // W2 transposed (overlays U.S, safe after barrier 1): W2T[c][hh] = W2[hh*64+c]
  for (int i = tid; i < 2048; i += NT)
    U.W2T[(i & 63) * WSTRIDE + (i >> 6)] = W2[i];
  __syncthreads();

  // ---- one row per warp: n = t + 128*m, m = (p>>7)*8 + w ----
  const int m = (p >> 7) * 8 + w;
  const int n = t + 128 * m;
  const float pre = __ldcg(&g_pre1[n * 32 + lane]);
  float a0 = 0.f, a1 = 0.f;
  const int b = n & 31;
  const bool sp = (n == 1024 * (b & 3) + 33 * b);   // steploss-special row
  const bool fg = ((n & 31) == (n >> 7));           // final-gather row
  float err = 0.f;
  const float sdt = 0.316227766016838f;

  const float4* wtRow = (const float4*)&sWT[lane * WSTRIDE];
  const float4* w2Row0 = (const float4*)&U.W2T[lane * WSTRIDE];
  const float4* w2Row1 = (const float4*)&U.W2T[(32 + lane) * WSTRIDE];
  const float4* accV = (const float4*)&sAcc[w][0];
  const float4* hV = (const float4*)&sH[w][0];

  for (int s = 0; s < NSTEPS; ++s) {
    const float tval = (float)s * 0.1f;
    // stage acc to per-warp smem
    sAcc[w][lane] = a0;
    sAcc[w][32 + lane] = a1;
    __syncwarp();

    // hidden: vectorized LDS.128 weights + broadcast acc
    float x0 = 0.f, x1 = 0.f, x2 = 0.f, x3 = 0.f;
#pragma unroll
    for (int k = 0; k < 16; ++k) {
      const float4 av = accV[k];
      const float4 wv = wtRow[k];
      x0 = fmaf(av.x, wv.x, x0);
      x1 = fmaf(av.y, wv.y, x1);
      x2 = fmaf(av.z, wv.z, x2);
      x3 = fmaf(av.w, wv.w, x3);
    }
    const float h = fmaxf(pre + tval * swts[lane] + ((x0 + x1) + (x2 + x3)), 0.0f);
    sH[w][lane] = h;
    __syncwarp();

    // score: vectorized over hh
    float p0 = 0.f, q0 = 0.f, p1 = 0.f, q1 = 0.f;
#pragma unroll
    for (int k = 0; k < 8; ++k) {
      const float4 hv = hV[k];
      const float4 wa = w2Row0[k];
      const float4 wb = w2Row1[k];
      p0 = fmaf(hv.x, wa.x, p0); q0 = fmaf(hv.y, wa.y, q0);
      p0 = fmaf(hv.z, wa.z, p0); q0 = fmaf(hv.w, wa.w, q0);
      p1 = fmaf(hv.x, wb.x, p1); q1 = fmaf(hv.y, wb.y, q1);
      p1 = fmaf(hv.z, wb.z, p1); q1 = fmaf(hv.w, wb.w, q1);
    }
    const float s0 = sb2s[lane] + (p0 + q0);
    const float s1 = sb2s[32 + lane] + (p1 + q1);

    // block rowsq partial -> hierarchical barrier+sum
    float rq = wred(fmaf(s0, s0, s1 * s1));
    if (lane == 0) sRed[w] = rq;
    __syncthreads();
    if (tid == 0) {
      float bp = ((sRed[0] + sRed[1]) + (sRed[2] + sRed[3])) +
                 ((sRed[4] + sRed[5]) + (sRed[6] + sRed[7]));
      sRed[0] = barrier_sum(2 + s, bp);
    }
    // noise overlaps tid0's barrier round-trip
    const unsigned k0 = K.k0[s], k1 = K.k1[s];
    const float dW0 = bits_to_normal(tfxor(k0, k1, (unsigned)(n * 64 + lane))) * sdt;
    const float dW1 = bits_to_normal(tfxor(k0, k1, (unsigned)(n * 64 + 32 + lane))) * sdt;
    __syncthreads();
    const float snorm = sqrtf(sRed[0]);

    a0 += 0.05f * s0 + snorm * dW0;
    a1 += 0.05f * s1 + snorm * dW1;

    if (sp) {
      float sq = wred(fmaf(a0, a0, a1 * a1));
      if (lane == 0) err += sq * (1.0f / 64.0f);
    }
  }

  // publish per-b step errors and final-gather acc rows
  if (sp && lane == 0) __stcg(&g_err32[b], err);
  if (fg) {
    __stcg(&g_accout[(n >> 5) * 64 + lane], a0);
    __stcg(&g_accout[(n >> 5) * 64 + 32 + lane], a1);
  }
  __threadfence();
  __syncthreads();
  if (tid == 0) { barrier_sum(12, 0.0f); }
  __syncthreads();
  __threadfence();

  // ---- finale sweep: out[b,i,d] + |emb - out| partials (2 elems/thread) ----
  {
    const int base = p * 512 + tid * 2;
    const int bb = base >> 13;
    const int ii = (base >> 6) & 127;
    const int jj = ii >> 2;
    const bool he = ii < 32 * (ii & 3) + bb;
    const bool ha = (jj == bb);
    float loc = 0.0f;
#pragma unroll
    for (int q = 0; q < 2; ++q) {
      const int d = (base & 63) + q;
      float v = 0.0f;
      if (he) v = emb[jj * 8192 + ii * 64 + d];
      if (ha) v += __ldcg(&g_accout[ii * 64 + d]);
      out[base + q] = v;
      loc += fabsf(emb[base + q] - v);
    }
    loc = wred(loc);
    if (lane == 0) sRed[w] = loc;
    __syncthreads();
    if (tid == 0) {
      float bp = ((sRed[0] + sRed[1]) + (sRed[2] + sRed[3])) +
                 ((sRed[4] + sRed[5]) + (sRed[6] + sRed[7]));
      __stcg(&g_abspart[p], bp);
      __threadfence();
      barrier_sum(13, 0.0f);
    }
    __syncthreads();
  }

  // block 0: parallel final reduction
  if (p == 0) {
    __threadfence();
    sRed[tid] = __ldcg(&g_abspart[tid]) + __ldcg(&g_abspart[tid + 256]);
    __syncthreads();
    for (int off = 128; off; off >>= 1) {
      if (tid < off) sRed[tid] += sRed[tid + off];
      __syncthreads();
    }
    float sl = 0.0f;
    if (tid < 32) sl = wred(__ldcg(&g_err32[tid]));
    if (tid == 0) {
      out[NELEMS] = sl;                                // step_loss
      out[NELEMS + 1] = sRed[0] * (1.0f / 262144.0f);  // sequence_loss
    }
  }
}

// ---------------- launch ----------------
extern "C" void kernel_launch(void* const* d_in, const int* in_sizes, int n_in,
                              void* d_out, int out_size) {
  const float* emb = (const float*)d_in[0];
  const float* W1  = (const float*)d_in[1];
  const float* b1  = (const float*)d_in[2];
  const float* W2  = (const float*)d_in[3];
  const float* b2  = (const float*)d_in[4];
  float* out = (float*)d_out;

  Keys K;
  for (int i = 0; i < NSTEPS; ++i)
    tf2x32(0u, 42u, 0u, (unsigned)i, &K.k0[i], &K.k1[i]);

  kFused<<<NB, NT>>>(emb, W1, b1, W2, b2, out, K);
}

// round 10
// speedup vs baseline: 1.1944x; 1.1944x over previous
#include <cuda_runtime.h>
#include <cstdint>

#define NSTEPS 10
#define NB     512     // all co-resident: 148 SMs x 4 blocks = 592 slots
#define NT     256
#define NBAR   14      // slot k reset by last arriver of barrier (k+1)%NBAR
#define NELEMS 262144
#define MASK52 ((1ull << 52) - 1ull)
#define CNT1   (1ull << 52)
#define WSTRIDE 76     // smem row stride (floats): float4-aligned, conflict-free

// ---------------- device scratch ----------------
__device__ float g_C[16 * 2048];
__device__ float g_pre1[4096 * 32];
__device__ float g_accout[128 * 64];
__device__ float g_err32[32];
__device__ float g_abspart[NB];
__device__ unsigned long long g_sync[NBAR];   // (count<<52 | fixed-point sum)

struct Keys { unsigned k0[NSTEPS]; unsigned k1[NSTEPS]; };

// ---------------- threefry2x32 ----------------
#define TF_ROT(x, r) (((x) << (r)) | ((x) >> (32 - (r))))
__host__ __device__ __forceinline__ void tf2x32(unsigned k0, unsigned k1,
                                                unsigned x0, unsigned x1,
                                                unsigned* o0, unsigned* o1) {
  unsigned ks0 = k0, ks1 = k1, ks2 = k0 ^ k1 ^ 0x1BD11BDAu;
  x0 += ks0; x1 += ks1;
#define TF_R4(a,b,c,d) \
  x0 += x1; x1 = TF_ROT(x1,a); x1 ^= x0; \
  x0 += x1; x1 = TF_ROT(x1,b); x1 ^= x0; \
  x0 += x1; x1 = TF_ROT(x1,c); x1 ^= x0; \
  x0 += x1; x1 = TF_ROT(x1,d); x1 ^= x0;
  TF_R4(13,15,26,6)  x0 += ks1; x1 += ks2 + 1u;
  TF_R4(17,29,16,24) x0 += ks2; x1 += ks0 + 2u;
  TF_R4(13,15,26,6)  x0 += ks0; x1 += ks1 + 3u;
  TF_R4(17,29,16,24) x0 += ks1; x1 += ks2 + 4u;
  TF_R4(13,15,26,6)  x0 += ks2; x1 += ks0 + 5u;
#undef TF_R4
  *o0 = x0; *o1 = x1;
}

__device__ __forceinline__ unsigned tfxor(unsigned k0, unsigned k1, unsigned e) {
  unsigned o0, o1;
  tf2x32(k0, k1, 0u, e, &o0, &o1);
  return o0 ^ o1;
}

__device__ __forceinline__ float bits_to_normal(unsigned bits) {
  float f = __uint_as_float((bits >> 9) | 0x3f800000u) - 1.0f;
  const float lo = __uint_as_float(0xBF7FFFFFu);
  float u = fmaxf(lo, f * 2.0f + lo);
  float w = -log1pf(-u * u);
  float p;
  if (w < 5.0f) {
    w -= 2.5f;
    p = 2.81022636e-08f;
    p = fmaf(p, w, 3.43273939e-07f);
    p = fmaf(p, w, -3.5233877e-06f);
    p = fmaf(p, w, -4.39150654e-06f);
    p = fmaf(p, w, 0.00021858087f);
    p = fmaf(p, w, -0.00125372503f);
    p = fmaf(p, w, -0.00417768164f);
    p = fmaf(p, w, 0.246640727f);
    p = fmaf(p, w, 1.50140941f);
  } else {
    w = sqrtf(w) - 3.0f;
    p = -0.000200214257f;
    p = fmaf(p, w, 0.000100950558f);
    p = fmaf(p, w, 0.00134934322f);
    p = fmaf(p, w, -0.00367342844f);
    p = fmaf(p, w, 0.00573950773f);
    p = fmaf(p, w, -0.0076224613f);
    p = fmaf(p, w, 0.00943887047f);
    p = fmaf(p, w, 1.00167406f);
    p = fmaf(p, w, 2.83297682f);
  }
  return 1.41421356237f * (p * u);
}

__device__ __forceinline__ float wred(float v) {
#pragma unroll
  for (int o = 16; o; o >>= 1) v += __shfl_xor_sync(0xffffffffu, v, o);
  return v;
}

// Flat fused barrier, combined arrive+poll (prologue/finale use).
__device__ __forceinline__ unsigned long long arrive_poll(int k, unsigned long long payload) {
  unsigned long long add = payload + CNT1;
  unsigned long long old = atomicAdd(&g_sync[k], add);
  if ((old >> 52) == (unsigned long long)(NB - 1)) {
    *((volatile unsigned long long*)&g_sync[(k + NBAR - 1) % NBAR]) = 0ull;
    return old + add;
  }
  unsigned long long v;
  do { v = *((volatile unsigned long long*)&g_sync[k]); } while ((v >> 52) < (unsigned long long)NB);
  return v;
}

// ---------------- the one fused kernel ----------------
__global__ void __launch_bounds__(NT, 4) kFused(
    const float* __restrict__ emb, const float* __restrict__ W1,
    const float* __restrict__ b1,  const float* __restrict__ W2,
    const float* __restrict__ b2,  float* __restrict__ out, Keys K) {
  __shared__ __align__(16) float sWT[32 * WSTRIDE];   // W1 tile transposed: [h][d]
  __shared__ __align__(16) union {
    float S[2048];
    float W2T[64 * WSTRIDE];
  } U;
  __shared__ __align__(16) float sSD[8][128];         // per-warp: score[0:64], dW[64:128]
  __shared__ __align__(16) float sH[8][32];           // per-warp hidden staging
  __shared__ float sRed[256];
  __shared__ float sb2s[64];
  __shared__ float swts[32];

  const int p = blockIdx.x;
  const int tid = threadIdx.x;
  const int lane = tid & 31, w = tid >> 5;
  const int t = p & 127;

  for (int i = tid; i < 2048; i += NT)
    sWT[(i & 31) * WSTRIDE + (i >> 5)] = W1[t * 2048 + i];
  if (tid < 64) sb2s[tid] = b2[tid];
  if (tid < 32) swts[tid] = W1[262144 + tid];

  // ---- P0: chunk sums ----
  if (p < 16) {
    for (int qq = tid; qq < 2048; qq += NT) {
      float s = 0.0f;
#pragma unroll
      for (int r = 0; r < 8; ++r) s += W1[(p * 8 + r) * 2048 + qq];
      __stcg(&g_C[p * 2048 + qq], s);
    }
    __threadfence();
  }
  __syncthreads();
  if (tid == 0) { arrive_poll(0, 0ull); }
  __syncthreads();
  __threadfence();

  // ---- P1: suffix sums + pre1 rows ----
  if (p < 128) {
    const int j = p, cj = j >> 3;
    for (int qq = tid; qq < 2048; qq += NT) {
      float s = 0.0f;
      for (int c = cj + 1; c < 16; ++c) s += __ldcg(&g_C[c * 2048 + qq]);
      for (int tt = j + 1; tt < cj * 8 + 8; ++tt) s += W1[tt * 2048 + qq];
      U.S[qq] = s;
    }
    __syncthreads();
    const int o = tid * 4;
    const int b = o >> 5, hh = o & 31;
    float v0 = b1[hh], v1 = b1[hh + 1], v2 = b1[hh + 2], v3 = b1[hh + 3];
    const float* er = emb + b * 8192 + j * 64;
#pragma unroll 8
    for (int d = 0; d < 64; ++d) {
      float ev = er[d];
      const float* spx = &U.S[d * 32 + hh];
      v0 = fmaf(ev, spx[0], v0); v1 = fmaf(ev, spx[1], v1);
      v2 = fmaf(ev, spx[2], v2); v3 = fmaf(ev, spx[3], v3);
    }
    float* pp = &g_pre1[(j * 32 + b) * 32 + hh];
    pp[0] = v0; pp[1] = v1; pp[2] = v2; pp[3] = v3;
    __threadfence();
  }
  __syncthreads();
  if (tid == 0) { arrive_poll(1, 0ull); }
  __syncthreads();
  __threadfence();

  // W2 transposed (overlays U.S after barrier 1)
  for (int i = tid; i < 2048; i += NT)
    U.W2T[(i & 63) * WSTRIDE + (i >> 6)] = W2[i];
  __syncthreads();

  // ---- one row per warp ----
  const int m = (p >> 7) * 8 + w;
  const int n = t + 128 * m;
  float P = __ldcg(&g_pre1[n * 32 + lane]);   // running pre-activation (no tval term)
  float a0 = 0.f, a1 = 0.f;
  const int b = n & 31;
  const bool sp = (n == 1024 * (b & 3) + 33 * b);
  const bool fg = ((n & 31) == (n >> 7));
  float err = 0.f;
  const float sdt = 0.316227766016838f;

  const float4* wtRow = (const float4*)&sWT[lane * WSTRIDE];
  const float4* w2Row0 = (const float4*)&U.W2T[lane * WSTRIDE];
  const float4* w2Row1 = (const float4*)&U.W2T[(32 + lane) * WSTRIDE];
  const float4* scV = (const float4*)&sSD[w][0];
  const float4* dwV = (const float4*)&sSD[w][64];
  const float4* hV = (const float4*)&sH[w][0];

  for (int s = 0; s < NSTEPS; ++s) {
    const float tval = (float)s * 0.1f;
    // LIGHT: hidden from running P (no matvec)
    const float h = fmaxf(P + tval * swts[lane], 0.0f);
    sH[w][lane] = h;
    __syncwarp();

    // LIGHT: score matvec
    float p0 = 0.f, q0 = 0.f, p1 = 0.f, q1 = 0.f;
#pragma unroll
    for (int k = 0; k < 8; ++k) {
      const float4 hv = hV[k];
      const float4 wa = w2Row0[k];
      const float4 wb = w2Row1[k];
      p0 = fmaf(hv.x, wa.x, p0); q0 = fmaf(hv.y, wa.y, q0);
      p0 = fmaf(hv.z, wa.z, p0); q0 = fmaf(hv.w, wa.w, q0);
      p1 = fmaf(hv.x, wb.x, p1); q1 = fmaf(hv.y, wb.y, q1);
      p1 = fmaf(hv.z, wb.z, p1); q1 = fmaf(hv.w, wb.w, q1);
    }
    const float s0 = sb2s[lane] + (p0 + q0);
    const float s1 = sb2s[32 + lane] + (p1 + q1);

    // LIGHT: rowsq -> non-blocking arrive
    float rq = wred(fmaf(s0, s0, s1 * s1));
    if (lane == 0) sRed[w] = rq;
    __syncthreads();
    unsigned long long myv = 0;
    if (tid == 0) {
      float bp = ((sRed[0] + sRed[1]) + (sRed[2] + sRed[3])) +
                 ((sRed[4] + sRed[5]) + (sRed[6] + sRed[7]));
      unsigned long long add = ((unsigned long long)(bp * 4294967296.0f)) + CNT1;
      myv = atomicAdd(&g_sync[2 + s], add) + add;
    }

    // HEAVY (overlaps barrier wait): threefry noise
    const unsigned k0 = K.k0[s], k1 = K.k1[s];
    const float dW0 = bits_to_normal(tfxor(k0, k1, (unsigned)(n * 64 + lane))) * sdt;
    const float dW1 = bits_to_normal(tfxor(k0, k1, (unsigned)(n * 64 + 32 + lane))) * sdt;
    sSD[w][lane] = s0;       sSD[w][32 + lane] = s1;
    sSD[w][64 + lane] = dW0; sSD[w][96 + lane] = dW1;
    __syncwarp();

    // HEAVY: fused dual matvec u = score.W1row, v = dW.W1row (shared weight loads)
    float u0 = 0.f, u1 = 0.f, v0 = 0.f, v1 = 0.f;
#pragma unroll
    for (int k = 0; k < 16; ++k) {
      const float4 wv = wtRow[k];
      const float4 sc = scV[k];
      const float4 dv = dwV[k];
      u0 = fmaf(sc.x, wv.x, u0); u1 = fmaf(sc.y, wv.y, u1);
      u0 = fmaf(sc.z, wv.z, u0); u1 = fmaf(sc.w, wv.w, u1);
      v0 = fmaf(dv.x, wv.x, v0); v1 = fmaf(dv.y, wv.y, v1);
      v0 = fmaf(dv.z, wv.z, v0); v1 = fmaf(dv.w, wv.w, v1);
    }
    const float uu = u0 + u1, vv = v0 + v1;

    // poll (tid0), broadcast snorm
    if (tid == 0) {
      unsigned long long v;
      if ((myv >> 52) == (unsigned long long)NB) {
        *((volatile unsigned long long*)&g_sync[(2 + s + NBAR - 1) % NBAR]) = 0ull;
        v = myv;
      } else {
        do { v = *((volatile unsigned long long*)&g_sync[2 + s]); }
        while ((v >> 52) < (unsigned long long)NB);
      }
      sRed[0] = (float)((double)(v & MASK52) * (1.0 / 4294967296.0));
    }
    __syncthreads();
    const float snorm = sqrtf(sRed[0]);

    // LIGHT: state update
    P += 0.05f * uu + snorm * vv;
    a0 += 0.05f * s0 + snorm * dW0;
    a1 += 0.05f * s1 + snorm * dW1;

    if (sp) {
      float sq = wred(fmaf(a0, a0, a1 * a1));
      if (lane == 0) err += sq * (1.0f / 64.0f);
    }
  }

  // publish outputs
  if (sp && lane == 0) __stcg(&g_err32[b], err);
  if (fg) {
    __stcg(&g_accout[(n >> 5) * 64 + lane], a0);
    __stcg(&g_accout[(n >> 5) * 64 + 32 + lane], a1);
  }
  __threadfence();
  __syncthreads();
  if (tid == 0) { arrive_poll(12, 0ull); }
  __syncthreads();
  __threadfence();

  // ---- finale sweep ----
  {
    const int base = p * 512 + tid * 2;
    const int bb = base >> 13;
    const int ii = (base >> 6) & 127;
    const int jj = ii >> 2;
    const bool he = ii < 32 * (ii & 3) + bb;
    const bool ha = (jj == bb);
    float loc = 0.0f;
#pragma unroll
    for (int q = 0; q < 2; ++q) {
      const int d = (base & 63) + q;
      float v = 0.0f;
      if (he) v = emb[jj * 8192 + ii * 64 + d];
      if (ha) v += __ldcg(&g_accout[ii * 64 + d]);
      out[base + q] = v;
      loc += fabsf(emb[base + q] - v);
    }
    loc = wred(loc);
    if (lane == 0) sRed[w] = loc;
    __syncthreads();
    if (tid == 0) {
      float bp = ((sRed[0] + sRed[1]) + (sRed[2] + sRed[3])) +
                 ((sRed[4] + sRed[5]) + (sRed[6] + sRed[7]));
      __stcg(&g_abspart[p], bp);
      __threadfence();
      arrive_poll(13, 0ull);
    }
    __syncthreads();
  }

  // block 0: final scalars
  if (p == 0) {
    __threadfence();
    sRed[tid] = __ldcg(&g_abspart[tid]) + __ldcg(&g_abspart[tid + 256]);
    __syncthreads();
    for (int off = 128; off; off >>= 1) {
      if (tid < off) sRed[tid] += sRed[tid + off];
      __syncthreads();
    }
    float sl = 0.0f;
    if (tid < 32) sl = wred(__ldcg(&g_err32[tid]));
    if (tid == 0) {
      out[NELEMS] = sl;
      out[NELEMS + 1] = sRed[0] * (1.0f / 262144.0f);
    }
  }
}

// ---------------- launch ----------------
extern "C" void kernel_launch(void* const* d_in, const int* in_sizes, int n_in,
                              void* d_out, int out_size) {
  const float* emb = (const float*)d_in[0];
  const float* W1  = (const float*)d_in[1];
  const float* b1  = (const float*)d_in[2];
  const float* W2  = (const float*)d_in[3];
  const float* b2  = (const float*)d_in[4];
  float* out = (float*)d_out;

  Keys K;
  for (int i = 0; i < NSTEPS; ++i)
    tf2x32(0u, 42u, 0u, (unsigned)i, &K.k0[i], &K.k1[i]);

  kFused<<<NB, NT>>>(emb, W1, b1, W2, b2, out, K);
}